// round 2
// baseline (speedup 1.0000x reference)
#include <cuda_runtime.h>
#include <cuda_bf16.h>
#include <cstdint>
#include <cstddef>

#define N_DIM     512
#define BATCH_DIM 16384
#define NROUND    511
#define NPAIR     256

// ---------------- scratch (static device globals; no runtime allocation) ----------------
__device__ __align__(16) float2        g_cs [NROUND * NPAIR];     // (cos, sin)
__device__ __align__(16) __nv_bfloat16 g_Uhi[N_DIM * N_DIM];      // U rows, bf16 hi
__device__ __align__(16) __nv_bfloat16 g_Ulo[N_DIM * N_DIM];      // U rows, bf16 lo
__device__ __align__(16) __nv_bfloat16 g_xhi[(size_t)BATCH_DIM * N_DIM];
__device__ __align__(16) __nv_bfloat16 g_xlo[(size_t)BATCH_DIM * N_DIM];

// ---------------- helpers ----------------
__device__ __forceinline__ uint32_t smem_u32(const void* p) {
    uint32_t a;
    asm("{ .reg .u64 t; cvta.to.shared.u64 t, %1; cvt.u32.u64 %0, t; }" : "=r"(a) : "l"(p));
    return a;
}

__device__ __forceinline__ void cp_async16(uint32_t s, const void* g) {
    asm volatile("cp.async.cg.shared.global [%0], [%1], 16;" :: "r"(s), "l"(g) : "memory");
}

__device__ __forceinline__ void ldm_x4(uint32_t* r, uint32_t addr) {
    asm volatile("ldmatrix.sync.aligned.m8n8.x4.shared.b16 {%0,%1,%2,%3}, [%4];"
                 : "=r"(r[0]), "=r"(r[1]), "=r"(r[2]), "=r"(r[3]) : "r"(addr));
}

__device__ __forceinline__ void mma16816(float* d, const uint32_t* a, uint32_t b0, uint32_t b1) {
    asm volatile(
        "mma.sync.aligned.m16n8k16.row.col.f32.bf16.bf16.f32 "
        "{%0,%1,%2,%3}, {%4,%5,%6,%7}, {%8,%9}, {%0,%1,%2,%3};"
        : "+f"(d[0]), "+f"(d[1]), "+f"(d[2]), "+f"(d[3])
        : "r"(a[0]), "r"(a[1]), "r"(a[2]), "r"(a[3]), "r"(b0), "r"(b1));
}

// ---------------- kernel 1: cos/sin precompute ----------------
__global__ void __launch_bounds__(256) cs_kernel(const float* __restrict__ angles) {
    int i = blockIdx.x * 256 + threadIdx.x;
    if (i < NROUND * NPAIR) {
        float s, c;
        sincosf(angles[i], &s, &c);
        g_cs[i] = make_float2(c, s);
    }
}

// ---------------- kernel 2: build U rows (one block per output row) ----------------
// Row o of U = e_o pushed through 511 rounds of disjoint pair rotations on columns.
__global__ void __launch_bounds__(256) build_u_kernel(const int* __restrict__ blocks) {
    __shared__ float row[N_DIM];
    const int t = threadIdx.x;
    const int o = blockIdx.x;
    row[t]       = (t == o)       ? 1.0f : 0.0f;
    row[t + 256] = (t + 256 == o) ? 1.0f : 0.0f;
    const int2* __restrict__ b2 = (const int2*)blocks;
    int2   id = b2[t];
    float2 cs = g_cs[t];
    __syncthreads();
    for (int r = 0; r < NROUND; r++) {
        const int nidx = (r + 1 < NROUND) ? (r + 1) * NPAIR + t : t;
        const int2   id_n = b2[nidx];
        const float2 cs_n = g_cs[nidx];
        const float ui = row[id.x];
        const float uj = row[id.y];
        row[id.x] = fmaf(cs.x, ui, cs.y * uj);
        row[id.y] = fmaf(cs.x, uj, -(cs.y * ui));
        __syncthreads();
        id = id_n; cs = cs_n;
    }
    for (int c = t; c < N_DIM; c += 256) {
        const float v = row[c];
        const __nv_bfloat16 h = __float2bfloat16(v);
        g_Uhi[o * N_DIM + c] = h;
        g_Ulo[o * N_DIM + c] = __float2bfloat16(v - __bfloat162float(h));
    }
}

// ---------------- kernel 3: split x into bf16 hi/lo ----------------
__global__ void __launch_bounds__(256) split_x_kernel(const float4* __restrict__ x4) {
    const int i = blockIdx.x * 256 + threadIdx.x;
    const float4 v = x4[i];
    __nv_bfloat16 h0 = __float2bfloat16(v.x);
    __nv_bfloat16 h1 = __float2bfloat16(v.y);
    __nv_bfloat16 h2 = __float2bfloat16(v.z);
    __nv_bfloat16 h3 = __float2bfloat16(v.w);
    __nv_bfloat16 l0 = __float2bfloat16(v.x - __bfloat162float(h0));
    __nv_bfloat16 l1 = __float2bfloat16(v.y - __bfloat162float(h1));
    __nv_bfloat16 l2 = __float2bfloat16(v.z - __bfloat162float(h2));
    __nv_bfloat16 l3 = __float2bfloat16(v.w - __bfloat162float(h3));
    __nv_bfloat162* H = (__nv_bfloat162*)g_xhi;
    __nv_bfloat162* L = (__nv_bfloat162*)g_xlo;
    __nv_bfloat162 a, b;
    a.x = h0; a.y = h1; b.x = h2; b.y = h3;
    H[2 * i] = a; H[2 * i + 1] = b;
    a.x = l0; a.y = l1; b.x = l2; b.y = l3;
    L[2 * i] = a; L[2 * i + 1] = b;
}

// ---------------- kernel 4: bf16x3 GEMM out = x @ U^T + bias ----------------
// mma.sync m16n8k16 path (sm_100 base target; tcgen05 unavailable without 'a' suffix).
// CTA tile 128x128, 8 warps (warpM 0..3, warpN 0..1), warp tile 32x64.
// K pipeline: KC=32, 4 cp.async stages, 48 chunk-iterations over 3 products:
//   phase 0: A=xhi,B=Uhi   phase 1: A=xhi,B=Ulo   phase 2: A=xlo,B=Uhi
#define KC          32
#define ROW_PITCH   80            // 64B data + 16B pad (bank-stride 20: conflict-free)
#define TILE_SB     (128 * ROW_PITCH)        // 10240 B per operand tile
#define STAGE_SB    (2 * TILE_SB)            // A + B
#define NSTAGE      4
#define GEMM_SMEM   (NSTAGE * STAGE_SB)      // 81920 B
#define NCHUNK      48

__device__ __forceinline__ void issue_chunk(uint32_t sbase, int i, int m0, int n0, int tid) {
    if (i < NCHUNK) {
        const int phase = i >> 4;
        const int kc    = i & 15;
        const __nv_bfloat16* Asrc = (phase == 2) ? g_xlo : g_xhi;
        const __nv_bfloat16* Bsrc = (phase == 1) ? g_Ulo : g_Uhi;
        const __nv_bfloat16* gA = Asrc + (size_t)m0 * N_DIM + kc * KC;
        const __nv_bfloat16* gB = Bsrc + (size_t)n0 * N_DIM + kc * KC;
        const uint32_t stage = sbase + (uint32_t)(i & (NSTAGE - 1)) * STAGE_SB;
        #pragma unroll
        for (int j = 0; j < 2; j++) {
            const int idx = tid + j * 256;       // 512 x 16B per tile
            const int row = idx >> 2;
            const int seg = idx & 3;
            const uint32_t soff = (uint32_t)(row * ROW_PITCH + seg * 16);
            cp_async16(stage + soff,            gA + (size_t)row * N_DIM + seg * 8);
            cp_async16(stage + TILE_SB + soff,  gB + (size_t)row * N_DIM + seg * 8);
        }
    }
    asm volatile("cp.async.commit_group;" ::: "memory");
}

__global__ void __launch_bounds__(256, 2) gemm_kernel(float* __restrict__ out,
                                                      const float* __restrict__ bias) {
    extern __shared__ char smem[];
    const uint32_t sb = smem_u32(smem);
    const int tid   = threadIdx.x;
    const int lane  = tid & 31;
    const int wid   = tid >> 5;
    const int warpM = wid & 3;
    const int warpN = wid >> 2;
    const int n0 = blockIdx.x * 128;
    const int m0 = blockIdx.y * 128;

    float acc[2][8][4];
    #pragma unroll
    for (int a = 0; a < 2; a++)
        #pragma unroll
        for (int b = 0; b < 8; b++)
            #pragma unroll
            for (int c = 0; c < 4; c++) acc[a][b][c] = 0.0f;

    // per-thread ldmatrix base offsets (row within tile, octet parity from lane)
    const int lrow  = lane & 15;
    const int loct  = lane >> 4;       // 0 or 1 -> +8 in k

    issue_chunk(sb, 0, m0, n0, tid);
    issue_chunk(sb, 1, m0, n0, tid);
    issue_chunk(sb, 2, m0, n0, tid);

    for (int i = 0; i < NCHUNK; i++) {
        asm volatile("cp.async.wait_group 2;" ::: "memory");
        __syncthreads();
        issue_chunk(sb, i + 3, m0, n0, tid);

        const uint32_t stage = sb + (uint32_t)(i & (NSTAGE - 1)) * STAGE_SB;
        const uint32_t sA = stage + (uint32_t)((warpM * 32 + lrow) * ROW_PITCH);
        const uint32_t sB = stage + TILE_SB + (uint32_t)((warpN * 64 + lrow) * ROW_PITCH);

        #pragma unroll
        for (int ks = 0; ks < 2; ks++) {
            const uint32_t koff = (uint32_t)((ks * 2 + loct) * 16);
            uint32_t afr[2][4], bfr[4][4];
            #pragma unroll
            for (int mi = 0; mi < 2; mi++)
                ldm_x4(afr[mi], sA + (uint32_t)(mi * 16 * ROW_PITCH) + koff);
            #pragma unroll
            for (int nj = 0; nj < 4; nj++)
                ldm_x4(bfr[nj], sB + (uint32_t)(nj * 16 * ROW_PITCH) + koff);
            #pragma unroll
            for (int mi = 0; mi < 2; mi++)
                #pragma unroll
                for (int t = 0; t < 8; t++) {
                    const int nj = t >> 1, hl = t & 1;
                    mma16816(acc[mi][t], afr[mi], bfr[nj][hl], bfr[nj][hl + 2]);
                }
        }
        __syncthreads();
    }

    // epilogue: direct coalesced-enough float2 stores + bias
    const int rbase = m0 + warpM * 32 + (lane >> 2);
    const int cbase = n0 + warpN * 64 + (lane & 3) * 2;
    #pragma unroll
    for (int mi = 0; mi < 2; mi++)
        #pragma unroll
        for (int t = 0; t < 8; t++) {
            const int col = cbase + t * 8;
            const float2 bv = __ldg((const float2*)&bias[col]);
            const int r0 = rbase + mi * 16;
            float2 v0, v1;
            v0.x = acc[mi][t][0] + bv.x; v0.y = acc[mi][t][1] + bv.y;
            v1.x = acc[mi][t][2] + bv.x; v1.y = acc[mi][t][3] + bv.y;
            *(float2*)&out[(size_t)r0 * N_DIM + col]       = v0;
            *(float2*)&out[(size_t)(r0 + 8) * N_DIM + col] = v1;
        }
}

// ---------------- launch ----------------
extern "C" void kernel_launch(void* const* d_in, const int* in_sizes, int n_in,
                              void* d_out, int out_size) {
    const float* x = nullptr;
    const float* angles = nullptr;
    const float* bias = nullptr;
    const int*   blocks = nullptr;
    for (int i = 0; i < n_in; i++) {
        const long sz = in_sizes[i];
        if      (sz == (long)BATCH_DIM * N_DIM)  x      = (const float*)d_in[i];
        else if (sz == (long)NROUND * NPAIR)     angles = (const float*)d_in[i];
        else if (sz == (long)N_DIM)              bias   = (const float*)d_in[i];
        else if (sz == (long)NROUND * NPAIR * 2) blocks = (const int*)d_in[i];
    }
    float* out = (float*)d_out;

    cs_kernel<<<(NROUND * NPAIR + 255) / 256, 256>>>(angles);
    build_u_kernel<<<N_DIM, 256>>>(blocks);
    split_x_kernel<<<(BATCH_DIM * N_DIM / 4 + 255) / 256, 256>>>((const float4*)x);
    cudaFuncSetAttribute(gemm_kernel, cudaFuncAttributeMaxDynamicSharedMemorySize, GEMM_SMEM);
    gemm_kernel<<<dim3(4, 128), 256, GEMM_SMEM>>>(out, bias);
}

// round 3
// speedup vs baseline: 1.0943x; 1.0943x over previous
#include <cuda_runtime.h>
#include <cuda_bf16.h>
#include <cstdint>
#include <cstddef>

#define N_DIM     512
#define BATCH_DIM 16384
#define NROUND    511
#define NPAIR     256

// ---------------- scratch (static device globals; no runtime allocation) ----------------
__device__ __align__(16) int2          g_sched[NROUND * NPAIR];   // oriented+bucketed (i,j)
__device__ __align__(16) float2        g_cs  [NROUND * NPAIR];    // matching (cos, sin')
__device__ __align__(16) __nv_bfloat16 g_Uhi[N_DIM * N_DIM];
__device__ __align__(16) __nv_bfloat16 g_Ulo[N_DIM * N_DIM];
__device__ __align__(16) __nv_bfloat16 g_xhi[(size_t)BATCH_DIM * N_DIM];
__device__ __align__(16) __nv_bfloat16 g_xlo[(size_t)BATCH_DIM * N_DIM];

// ---------------- helpers ----------------
__device__ __forceinline__ uint32_t smem_u32(const void* p) {
    uint32_t a;
    asm("{ .reg .u64 t; cvta.to.shared.u64 t, %1; cvt.u32.u64 %0, t; }" : "=r"(a) : "l"(p));
    return a;
}

__device__ __forceinline__ void cp_async16(uint32_t s, const void* g) {
    asm volatile("cp.async.cg.shared.global [%0], [%1], 16;" :: "r"(s), "l"(g) : "memory");
}

__device__ __forceinline__ void ldm_x4(uint32_t* r, uint32_t addr) {
    asm volatile("ldmatrix.sync.aligned.m8n8.x4.shared.b16 {%0,%1,%2,%3}, [%4];"
                 : "=r"(r[0]), "=r"(r[1]), "=r"(r[2]), "=r"(r[3]) : "r"(addr));
}

__device__ __forceinline__ void mma16816(float* d, const uint32_t* a, uint32_t b0, uint32_t b1) {
    asm volatile(
        "mma.sync.aligned.m16n8k16.row.col.f32.bf16.bf16.f32 "
        "{%0,%1,%2,%3}, {%4,%5,%6,%7}, {%8,%9}, {%0,%1,%2,%3};"
        : "+f"(d[0]), "+f"(d[1]), "+f"(d[2]), "+f"(d[3])
        : "r"(a[0]), "r"(a[1]), "r"(a[2]), "r"(a[3]), "r"(b0), "r"(b1));
}

// ---------------- kernel 1: per-round conflict-aware scheduling + sincos ----------------
// For each round: orient pairs ((i,j) <-> (j,i), s -> -s) so i-side banks balance to 8
// per bank, then slot = occ*32 + bank  ==>  each warp's 32 i-accesses are conflict-free.
__global__ void __launch_bounds__(NPAIR) sched_kernel(const int* __restrict__ blocks,
                                                      const float* __restrict__ angles) {
    __shared__ int  cnt[32];
    __shared__ unsigned char taken[NPAIR];
    __shared__ int  sfree[NPAIR];
    __shared__ int  nfree, ovfp;
    const int r = blockIdx.x;
    const int t = threadIdx.x;
    if (t < 32) cnt[t] = 0;
    taken[t] = 0;
    if (t == 0) { nfree = 0; ovfp = 0; }
    __syncthreads();

    const int i = blocks[(r * NPAIR + t) * 2];
    const int j = blocks[(r * NPAIR + t) * 2 + 1];
    float s, c;
    sincosf(angles[r * NPAIR + t], &s, &c);
    const int bi = i & 31, bj = j & 31;

    int slot = -1, swapped = 0;
    const int pref_first = (cnt[bi] <= cnt[bj]);   // racy heuristic read, correctness-neutral
    const int b0 = pref_first ? bi : bj;
    int occ = atomicAdd(&cnt[b0], 1);
    if (occ < 8) {
        slot = occ * 32 + b0; swapped = pref_first ? 0 : 1;
    } else {
        atomicSub(&cnt[b0], 1);
        const int b1 = pref_first ? bj : bi;
        occ = atomicAdd(&cnt[b1], 1);
        if (occ < 8) { slot = occ * 32 + b1; swapped = pref_first ? 1 : 0; }
        else atomicSub(&cnt[b1], 1);
    }
    if (slot >= 0) taken[slot] = 1;
    __syncthreads();
    if (!taken[t]) { int k = atomicAdd(&nfree, 1); sfree[k] = t; }
    __syncthreads();
    if (slot < 0) { int k = atomicAdd(&ovfp, 1); slot = sfree[k]; }

    int2 od; od.x = swapped ? j : i; od.y = swapped ? i : j;
    g_sched[r * NPAIR + slot] = od;
    g_cs  [r * NPAIR + slot] = make_float2(c, swapped ? -s : s);
}

// ---------------- kernel 2 (fused): build U rows  +  split x into bf16 hi/lo ----------------
__global__ void __launch_bounds__(256) build_split_kernel(const float4* __restrict__ x4) {
    const int t = threadIdx.x;
    if (blockIdx.x < N_DIM) {
        // ---- build one U row ----
        __shared__ float row[N_DIM];
        const int o = blockIdx.x;
        row[t]       = (t == o)       ? 1.0f : 0.0f;
        row[t + 256] = (t + 256 == o) ? 1.0f : 0.0f;
        int2   id = g_sched[t];
        float2 cs = g_cs[t];
        __syncthreads();
        for (int r = 0; r < NROUND; r++) {
            const int nidx = (r + 1 < NROUND) ? (r + 1) * NPAIR + t : t;
            const int2   id_n = g_sched[nidx];
            const float2 cs_n = g_cs[nidx];
            const float ui = row[id.x];
            const float uj = row[id.y];
            row[id.x] = fmaf(cs.x, ui, cs.y * uj);
            row[id.y] = fmaf(cs.x, uj, -(cs.y * ui));
            __syncthreads();
            id = id_n; cs = cs_n;
        }
        for (int cidx = t; cidx < N_DIM; cidx += 256) {
            const float v = row[cidx];
            const __nv_bfloat16 h = __float2bfloat16(v);
            g_Uhi[o * N_DIM + cidx] = h;
            g_Ulo[o * N_DIM + cidx] = __float2bfloat16(v - __bfloat162float(h));
        }
    } else {
        // ---- split a chunk of x (overlaps with U build; independent work) ----
        const int bs = blockIdx.x - N_DIM;                  // 0..511
        const int base = bs * 256 * 16;                     // float4 index base
        #pragma unroll 4
        for (int k = 0; k < 16; k++) {
            const int idx = base + k * 256 + t;             // exact cover of 2^21 float4
            const float4 v = x4[idx];
            __nv_bfloat16 h0 = __float2bfloat16(v.x);
            __nv_bfloat16 h1 = __float2bfloat16(v.y);
            __nv_bfloat16 h2 = __float2bfloat16(v.z);
            __nv_bfloat16 h3 = __float2bfloat16(v.w);
            __nv_bfloat162 a, b;
            a.x = h0; a.y = h1; b.x = h2; b.y = h3;
            ((__nv_bfloat162*)g_xhi)[2 * idx]     = a;
            ((__nv_bfloat162*)g_xhi)[2 * idx + 1] = b;
            a.x = __float2bfloat16(v.x - __bfloat162float(h0));
            a.y = __float2bfloat16(v.y - __bfloat162float(h1));
            b.x = __float2bfloat16(v.z - __bfloat162float(h2));
            b.y = __float2bfloat16(v.w - __bfloat162float(h3));
            ((__nv_bfloat162*)g_xlo)[2 * idx]     = a;
            ((__nv_bfloat162*)g_xlo)[2 * idx + 1] = b;
        }
    }
}

// ---------------- kernel 3: bf16x3 GEMM out = x @ U^T + bias ----------------
// CTA 128x128, 8 warps (warp 32x64), KC=64, 3-stage cp.async pipeline (depth-2 prefetch).
#define KC        64
#define PITCH     144                       // 128B data + 16B pad (36-word stride: ldmatrix conflict-free)
#define ATILE     (128 * PITCH)             // 18432 B
#define STAGE_SB  (2 * ATILE)               // A + B = 36864 B
#define NSTAGE    3
#define GEMM_SMEM (NSTAGE * STAGE_SB)       // 110592 B
#define NCHUNK    24                        // 3 products x 8 k-chunks

__device__ __forceinline__ void issue_chunk(uint32_t sbase, int i, int m0, int n0, int tid) {
    if (i < NCHUNK) {
        const int phase = i >> 3;
        const int kc    = i & 7;
        const __nv_bfloat16* Asrc = (phase == 2) ? g_xlo : g_xhi;
        const __nv_bfloat16* Bsrc = (phase == 1) ? g_Ulo : g_Uhi;
        const __nv_bfloat16* gA = Asrc + (size_t)m0 * N_DIM + kc * KC;
        const __nv_bfloat16* gB = Bsrc + (size_t)n0 * N_DIM + kc * KC;
        const uint32_t stage = sbase + (uint32_t)(i % NSTAGE) * STAGE_SB;
        #pragma unroll
        for (int tt = 0; tt < 4; tt++) {                    // A: 1024 x 16B
            const int idx = tid + tt * 256;
            const int row = idx >> 3, seg = idx & 7;
            cp_async16(stage + (uint32_t)(row * PITCH + seg * 16),
                       gA + (size_t)row * N_DIM + seg * 8);
        }
        #pragma unroll
        for (int tt = 0; tt < 4; tt++) {                    // B: 1024 x 16B
            const int idx = tid + tt * 256;
            const int row = idx >> 3, seg = idx & 7;
            cp_async16(stage + ATILE + (uint32_t)(row * PITCH + seg * 16),
                       gB + (size_t)row * N_DIM + seg * 8);
        }
    }
    asm volatile("cp.async.commit_group;" ::: "memory");
}

__global__ void __launch_bounds__(256, 2) gemm_kernel(float* __restrict__ out,
                                                      const float* __restrict__ bias) {
    extern __shared__ char smem[];
    const uint32_t sb = smem_u32(smem);
    const int tid   = threadIdx.x;
    const int lane  = tid & 31;
    const int wid   = tid >> 5;
    const int warpM = wid & 3;
    const int warpN = wid >> 2;
    const int n0 = blockIdx.x * 128;
    const int m0 = blockIdx.y * 128;

    float acc[2][8][4];
    #pragma unroll
    for (int a = 0; a < 2; a++)
        #pragma unroll
        for (int b = 0; b < 8; b++)
            #pragma unroll
            for (int c = 0; c < 4; c++) acc[a][b][c] = 0.0f;

    const int lrow = lane & 15;
    const int loct = lane >> 4;

    issue_chunk(sb, 0, m0, n0, tid);
    issue_chunk(sb, 1, m0, n0, tid);

    for (int i = 0; i < NCHUNK; i++) {
        issue_chunk(sb, i + 2, m0, n0, tid);
        asm volatile("cp.async.wait_group 2;" ::: "memory");
        __syncthreads();

        const uint32_t stage = sb + (uint32_t)(i % NSTAGE) * STAGE_SB;
        const uint32_t sA = stage + (uint32_t)((warpM * 32 + lrow) * PITCH);
        const uint32_t sB = stage + ATILE + (uint32_t)((warpN * 64 + lrow) * PITCH);

        #pragma unroll
        for (int ks = 0; ks < 4; ks++) {
            const uint32_t koff = (uint32_t)(ks * 32 + loct * 16);
            uint32_t afr[2][4], bfr[4][4];
            #pragma unroll
            for (int mi = 0; mi < 2; mi++)
                ldm_x4(afr[mi], sA + (uint32_t)(mi * 16 * PITCH) + koff);
            #pragma unroll
            for (int nj = 0; nj < 4; nj++)
                ldm_x4(bfr[nj], sB + (uint32_t)(nj * 16 * PITCH) + koff);
            #pragma unroll
            for (int mi = 0; mi < 2; mi++)
                #pragma unroll
                for (int t = 0; t < 8; t++) {
                    const int nj = t >> 1, hl = t & 1;
                    mma16816(acc[mi][t], afr[mi], bfr[nj][hl], bfr[nj][hl + 2]);
                }
        }
        __syncthreads();
    }

    const int rbase = m0 + warpM * 32 + (lane >> 2);
    const int cbase = n0 + warpN * 64 + (lane & 3) * 2;
    #pragma unroll
    for (int mi = 0; mi < 2; mi++)
        #pragma unroll
        for (int t = 0; t < 8; t++) {
            const int col = cbase + t * 8;
            const float2 bv = __ldg((const float2*)&bias[col]);
            const int r0 = rbase + mi * 16;
            float2 v0, v1;
            v0.x = acc[mi][t][0] + bv.x; v0.y = acc[mi][t][1] + bv.y;
            v1.x = acc[mi][t][2] + bv.x; v1.y = acc[mi][t][3] + bv.y;
            *(float2*)&out[(size_t)r0 * N_DIM + col]       = v0;
            *(float2*)&out[(size_t)(r0 + 8) * N_DIM + col] = v1;
        }
}

// ---------------- launch ----------------
extern "C" void kernel_launch(void* const* d_in, const int* in_sizes, int n_in,
                              void* d_out, int out_size) {
    const float* x = nullptr;
    const float* angles = nullptr;
    const float* bias = nullptr;
    const int*   blocks = nullptr;
    for (int i = 0; i < n_in; i++) {
        const long sz = in_sizes[i];
        if      (sz == (long)BATCH_DIM * N_DIM)  x      = (const float*)d_in[i];
        else if (sz == (long)NROUND * NPAIR)     angles = (const float*)d_in[i];
        else if (sz == (long)N_DIM)              bias   = (const float*)d_in[i];
        else if (sz == (long)NROUND * NPAIR * 2) blocks = (const int*)d_in[i];
    }
    float* out = (float*)d_out;

    sched_kernel<<<NROUND, NPAIR>>>(blocks, angles);
    build_split_kernel<<<N_DIM + 512, 256>>>((const float4*)x);
    cudaFuncSetAttribute(gemm_kernel, cudaFuncAttributeMaxDynamicSharedMemorySize, GEMM_SMEM);
    gemm_kernel<<<dim3(4, 128), 256, GEMM_SMEM>>>(out, bias);
}